// round 10
// baseline (speedup 1.0000x reference)
#include <cuda_runtime.h>
#include <cuda_fp16.h>
#include <math.h>
#include <stdint.h>

#define BSZ  2
#define SEQL 2048
#define DIMM 4096
#define NH   32
#define NKV  8
#define HD   128
#define MTOT (BSZ * SEQL)          // 4096
#define NQKV (NH * HD + 2 * NKV * HD)   // 6144

// ---------------- scratch (__device__ globals) ----------------------------
__device__ __half g_xh[MTOT * DIMM];
__device__ __half g_wqkvh[DIMM * NQKV];
__device__ __half g_woh[DIMM * DIMM];
__device__ __half g_attnh[MTOT * NH * HD];
__device__ __half g_qh[MTOT * NH * HD];
__device__ __half g_kh[MTOT * NKV * HD];
__device__ __half g_vh[MTOT * NKV * HD];

// ---------------- PTX helpers ---------------------------------------------
__device__ __forceinline__ uint32_t smem_u32(const void* p) {
    uint32_t a;
    asm("{ .reg .u64 t; cvta.to.shared.u64 t, %1; cvt.u32.u64 %0, t; }"
        : "=r"(a) : "l"(p));
    return a;
}
__device__ __forceinline__ void cp_async16(uint32_t dst, const void* src) {
    asm volatile("cp.async.cg.shared.global [%0], [%1], 16;" :: "r"(dst), "l"(src));
}
#define CP_COMMIT() asm volatile("cp.async.commit_group;" ::: "memory")
#define CP_WAIT(n)  asm volatile("cp.async.wait_group %0;" :: "n"(n) : "memory")

#define LDSM_X4(R, addr) \
    asm volatile("ldmatrix.sync.aligned.m8n8.x4.shared.b16 {%0,%1,%2,%3}, [%4];" \
        : "=r"((R)[0]), "=r"((R)[1]), "=r"((R)[2]), "=r"((R)[3]) : "r"(addr))
#define LDSM_X4_T(R, addr) \
    asm volatile("ldmatrix.sync.aligned.m8n8.x4.trans.shared.b16 {%0,%1,%2,%3}, [%4];" \
        : "=r"((R)[0]), "=r"((R)[1]), "=r"((R)[2]), "=r"((R)[3]) : "r"(addr))

#define MMA16816(D, A, B0, B1) \
    asm volatile("mma.sync.aligned.m16n8k16.row.col.f32.f16.f16.f32 " \
        "{%0,%1,%2,%3}, {%4,%5,%6,%7}, {%8,%9}, {%0,%1,%2,%3};" \
        : "+f"((D)[0]), "+f"((D)[1]), "+f"((D)[2]), "+f"((D)[3]) \
        : "r"((A)[0]), "r"((A)[1]), "r"((A)[2]), "r"((A)[3]), "r"(B0), "r"(B1))

// ------ fp16 mma.sync GEMM, 128x128 tile, 4 warps (64x64 each), 2 CTAs/SM --
// MODE 0: C fp32 out. MODE 1: fused RoPE + fp16 split epilogue (q|k|v).
#define GBM 128
#define GBN 128
#define GBK 64
#define GST 3
#define A_STAGE 16384                      // 128 rows * 128 B
#define B_STAGE 16384                      // 64 rows * 2 blocks * 128 B
#define STAGE_BYTES (A_STAGE + B_STAGE)    // 32768
#define GEMM_SMEM (GST * STAGE_BYTES)      // 98304

template<int MODE>
__global__ __launch_bounds__(128, 2) void gemm_f16_128(
    const __half* __restrict__ A, const __half* __restrict__ B,
    float* __restrict__ C,
    __half* __restrict__ Qd, __half* __restrict__ Kd, __half* __restrict__ Vd,
    const float* __restrict__ cosb, const float* __restrict__ sinb,
    int M, int N, int K)
{
    extern __shared__ char smem[];
    const uint32_t sb = smem_u32(smem);
    const int tid  = threadIdx.x;
    const int lane = tid & 31;
    const int wid  = tid >> 5;          // 0..3
    const int mt   = blockIdx.y * GBM;
    const int nt   = blockIdx.x * GBN;
    const int wm   = (wid >> 1) * 64;   // 2x2 warp grid, 64x64 warp tile
    const int wn   = (wid & 1) * 64;
    const int NK   = K / GBK;

    float acc[4][8][4];
#pragma unroll
    for (int i = 0; i < 4; i++)
#pragma unroll
        for (int j = 0; j < 8; j++)
#pragma unroll
            for (int c = 0; c < 4; c++) acc[i][j][c] = 0.f;

    auto load_stage = [&](int kt, int s) {
        const uint32_t as = sb + s * STAGE_BYTES;
        const uint32_t bs = as + A_STAGE;
        const __half* Ag = A + (size_t)mt * K + kt * GBK;
        const __half* Bg = B + (size_t)(kt * GBK) * N + nt;
#pragma unroll
        for (int i = 0; i < 8; i++) {          // A: 1024 16B chunks
            int id = tid + i * 128;
            int r = id >> 3, c = id & 7;
            cp_async16(as + r * 128 + ((c ^ (r & 7)) << 4),
                       Ag + (size_t)r * K + c * 8);
        }
#pragma unroll
        for (int i = 0; i < 8; i++) {          // B: 1024 16B chunks
            int id = tid + i * 128;
            int r = id >> 4, c = id & 15;
            uint32_t dst = bs + (c >> 3) * 8192 + r * 128 +
                           (((c & 7) ^ (r & 7)) << 4);
            cp_async16(dst, Bg + (size_t)r * N + c * 8);
        }
        CP_COMMIT();
    };

    load_stage(0, 0);
    load_stage(1, 1);

    const int lr = lane & 15;
    const int lq = lane >> 4;

    int st = 0;
    for (int kt = 0; kt < NK; kt++) {
        CP_WAIT(1);
        __syncthreads();
        if (kt + 2 < NK) {
            int s2 = st + 2; if (s2 >= GST) s2 -= GST;
            load_stage(kt + 2, s2);
        }

        const uint32_t as = sb + st * STAGE_BYTES;
        const uint32_t bs = as + A_STAGE;

#pragma unroll
        for (int ks = 0; ks < 4; ks++) {
            const int kk = ks * 16;
            uint32_t ar[4][4];
#pragma unroll
            for (int mf = 0; mf < 4; mf++) {
                int r = wm + mf * 16 + lr;
                LDSM_X4(ar[mf], as + r * 128 + ((((kk >> 3) + lq) ^ (r & 7)) << 4));
            }
            uint32_t br[4][4];
#pragma unroll
            for (int nf2 = 0; nf2 < 4; nf2++) {
                int n0 = wn + nf2 * 16;
                int r  = kk + lr;
                int cc = ((n0 & 63) >> 3) + lq;
                LDSM_X4_T(br[nf2], bs + ((n0 >= 64) ? 8192 : 0) + r * 128 +
                                   ((cc ^ (r & 7)) << 4));
            }
#pragma unroll
            for (int mf = 0; mf < 4; mf++)
#pragma unroll
                for (int nf = 0; nf < 8; nf++) {
                    uint32_t b0 = br[nf >> 1][(nf & 1) * 2];
                    uint32_t b1 = br[nf >> 1][(nf & 1) * 2 + 1];
                    MMA16816(acc[mf][nf], ar[mf], b0, b1);
                }
        }
        if (++st == GST) st = 0;
    }

    const int g   = lane >> 2;
    const int tq  = lane & 3;

    if (MODE == 0) {
#pragma unroll
        for (int mf = 0; mf < 4; mf++) {
            int row0 = mt + wm + mf * 16 + g;
#pragma unroll
            for (int nf = 0; nf < 8; nf++) {
                int col = nt + wn + nf * 8 + tq * 2;
                *(float2*)(C + (size_t)row0 * N + col) =
                    make_float2(acc[mf][nf][0], acc[mf][nf][1]);
                *(float2*)(C + (size_t)(row0 + 8) * N + col) =
                    make_float2(acc[mf][nf][2], acc[mf][nf][3]);
            }
        }
    } else {
        // region: q cols [0,4096), k [4096,5120), v [5120,6144) — tile-aligned
        const int region = (nt >= 5 * 1024) ? 2 : (nt >= 4 * 1024 ? 1 : 0);
        __half* dst = region == 0 ? Qd : (region == 1 ? Kd : Vd);
        const int ld = region == 0 ? NH * HD : NKV * HD;
        const int cb = nt - (region == 0 ? 0 : (region == 1 ? 4096 : 5120));
        const bool dorope = (region < 2);
#pragma unroll
        for (int mf = 0; mf < 4; mf++) {
            int r0 = mt + wm + mf * 16 + g;
            int s0 = r0 & (SEQL - 1);
            int s1 = (r0 + 8) & (SEQL - 1);
#pragma unroll
            for (int nf = 0; nf < 8; nf++) {
                int colg = wn + nf * 8 + tq * 2;
                float a0 = acc[mf][nf][0], a1 = acc[mf][nf][1];
                float a2 = acc[mf][nf][2], a3 = acc[mf][nf][3];
                __half2 h0, h1;
                if (dorope) {
                    int i = ((nt + colg) & 127) >> 1;
                    float c0 = cosb[s0 * 64 + i], n0 = sinb[s0 * 64 + i];
                    float c1 = cosb[s1 * 64 + i], n1 = sinb[s1 * 64 + i];
                    h0 = __floats2half2_rn(a0 * c0 - a1 * n0, a0 * n0 + a1 * c0);
                    h1 = __floats2half2_rn(a2 * c1 - a3 * n1, a2 * n1 + a3 * c1);
                } else {
                    h0 = __floats2half2_rn(a0, a1);
                    h1 = __floats2half2_rn(a2, a3);
                }
                *(__half2*)(dst + (size_t)r0 * ld + cb + colg) = h0;
                *(__half2*)(dst + (size_t)(r0 + 8) * ld + cb + colg) = h1;
            }
        }
    }
}

// ---------------- one fused fp32 -> fp16 convert kernel (4 chunks/thread) --
#define CNX  (MTOT * DIMM / 8)
#define CNWO (DIMM * DIMM / 8)
#define CNWQ (DIMM * NH * HD / 8)
#define CNWK (DIMM * NKV * HD / 8)
#define CTOT (CNX + CNWO + CNWQ + 2 * CNWK)
#define CQ   (CTOT / 4)

__device__ __forceinline__ uint4 cvt8(const float* p) {
    float4 v0 = ((const float4*)p)[0];
    float4 v1 = ((const float4*)p)[1];
    union { uint4 u; __half2 h[4]; } r;
    r.h[0] = __floats2half2_rn(v0.x, v0.y);
    r.h[1] = __floats2half2_rn(v0.z, v0.w);
    r.h[2] = __floats2half2_rn(v1.x, v1.y);
    r.h[3] = __floats2half2_rn(v1.z, v1.w);
    return r.u;
}

__device__ __forceinline__ void do_chunk(
    int i, const float* x, const float* wq, const float* wk,
    const float* wv, const float* wo,
    __half* xh, __half* wqkvh, __half* woh)
{
    if (i < CNX) {
        ((uint4*)xh)[i] = cvt8(x + (size_t)i * 8);
    } else if (i < CNX + CNWO) {
        int j = i - CNX;
        ((uint4*)woh)[j] = cvt8(wo + (size_t)j * 8);
    } else if (i < CNX + CNWO + CNWQ) {
        int j = i - CNX - CNWO;
        int r = j >> 9, c = j & 511;
        *(uint4*)(wqkvh + (size_t)r * NQKV + c * 8) = cvt8(wq + (size_t)j * 8);
    } else if (i < CNX + CNWO + CNWQ + CNWK) {
        int j = i - CNX - CNWO - CNWQ;
        int r = j >> 7, c = j & 127;
        *(uint4*)(wqkvh + (size_t)r * NQKV + 4096 + c * 8) = cvt8(wk + (size_t)j * 8);
    } else {
        int j = i - CNX - CNWO - CNWQ - CNWK;
        int r = j >> 7, c = j & 127;
        *(uint4*)(wqkvh + (size_t)r * NQKV + 5120 + c * 8) = cvt8(wv + (size_t)j * 8);
    }
}

__global__ void convert_all(const float* __restrict__ x,
                            const float* __restrict__ wq,
                            const float* __restrict__ wk,
                            const float* __restrict__ wv,
                            const float* __restrict__ wo,
                            __half* __restrict__ xh,
                            __half* __restrict__ wqkvh,
                            __half* __restrict__ woh)
{
    int i = blockIdx.x * blockDim.x + threadIdx.x;
    if (i >= CQ) return;
    do_chunk(i,          x, wq, wk, wv, wo, xh, wqkvh, woh);
    do_chunk(i + CQ,     x, wq, wk, wv, wo, xh, wqkvh, woh);
    do_chunk(i + 2 * CQ, x, wq, wk, wv, wo, xh, wqkvh, woh);
    do_chunk(i + 3 * CQ, x, wq, wk, wv, wo, xh, wqkvh, woh);
}

// ---------------- fp16 tensor-core flash attention, FK=128 -----------------
#define FQ 128
#define FK 128
#define QBYTES   (FQ * 256)                // 32768
#define KVSTAGE  (FK * 256 * 2)            // 65536 (K 32KB + V 32KB)
#define FA_SMEM  (QBYTES + 2 * KVSTAGE)    // 163840

__device__ __forceinline__ uint32_t swz(uint32_t c, uint32_t r) {
    return ((c ^ (r & 7)) & 7) | (c & 8);
}

__global__ __launch_bounds__(256, 1) void flash_f16(
    const __half* __restrict__ Qh, const __half* __restrict__ Kh,
    const __half* __restrict__ Vh, __half* __restrict__ Oh, int seq)
{
    extern __shared__ char smc[];
    const uint32_t sb = smem_u32(smc);
    const uint32_t Qs = sb;

    const int nq = seq / FQ;
    const int qt = nq - 1 - blockIdx.x;       // longest CTAs first
    const int h = blockIdx.y, b = blockIdx.z;
    const int kvh = h >> 2;
    const int tid = threadIdx.x, lane = tid & 31, wid = tid >> 5;
    const int lr = lane & 15, lq = lane >> 4;
    const int g = lane >> 2, tq = lane & 3;
    const float scale = 0.08838834764831845f;

    const __half* Qg = Qh + ((size_t)(b * seq + qt * FQ) * NH + h) * HD;
    const __half* Kg = Kh + ((size_t)b * seq * NKV + kvh) * HD;
    const __half* Vg = Vh + ((size_t)b * seq * NKV + kvh) * HD;

#pragma unroll
    for (int i = 0; i < 8; i++) {
        int id = tid + i * 256;
        int r = id >> 4, c = id & 15;
        cp_async16(Qs + r * 256 + swz(c, r) * 16, Qg + (size_t)r * (NH * HD) + c * 8);
    }
    CP_COMMIT();

    auto load_kv = [&](int kt, int s) {
        uint32_t ks = sb + QBYTES + s * KVSTAGE;
        uint32_t vs = ks + FK * 256;
        const __half* kg = Kg + (size_t)(kt * FK) * (NKV * HD);
        const __half* vg = Vg + (size_t)(kt * FK) * (NKV * HD);
#pragma unroll
        for (int i = 0; i < 8; i++) {
            int id = tid + i * 256;
            int r = id >> 4, c = id & 15;
            uint32_t off = r * 256 + swz(c, r) * 16;
            cp_async16(ks + off, kg + (size_t)r * (NKV * HD) + c * 8);
            cp_async16(vs + off, vg + (size_t)r * (NKV * HD) + c * 8);
        }
        CP_COMMIT();
    };

    const int ntiles = qt + 1;
    load_kv(0, 0);

    float acc_o[16][4];
#pragma unroll
    for (int d = 0; d < 16; d++)
#pragma unroll
        for (int c = 0; c < 4; c++) acc_o[d][c] = 0.f;
    float mrow[2] = {-1e30f, -1e30f};
    float lrow[2] = {0.f, 0.f};

    const int row0 = qt * FQ + wid * 16 + g;

    for (int kt = 0; kt < ntiles; kt++) {
        if (kt + 1 < ntiles) { load_kv(kt + 1, (kt + 1) & 1); CP_WAIT(1); }
        else                 { CP_WAIT(0); }
        __syncthreads();

        const uint32_t ks = sb + QBYTES + (kt & 1) * KVSTAGE;
        const uint32_t vs = ks + FK * 256;

        // ---- S = Q @ K^T  (warp tile 16 x 128) ----
        float accs[16][4];
#pragma unroll
        for (int j = 0; j < 16; j++)
#pragma unroll
            for (int c = 0; c < 4; c++) accs[j][c] = 0.f;

#pragma unroll
        for (int d = 0; d < 8; d++) {
            uint32_t a[4];
            {
                int r = wid * 16 + lr;
                LDSM_X4(a, Qs + r * 256 + swz(d * 2 + lq, r) * 16);
            }
#pragma unroll
            for (int n = 0; n < 8; n++) {
                uint32_t kb[4];
                int r = n * 16 + lr;
                LDSM_X4(kb, ks + r * 256 + swz(d * 2 + lq, r) * 16);
                MMA16816(accs[n * 2],     a, kb[0], kb[2]);
                MMA16816(accs[n * 2 + 1], a, kb[1], kb[3]);
            }
        }

        // ---- online softmax ----
        const bool need_mask = (kt == qt);
#pragma unroll
        for (int rr = 0; rr < 2; rr++) {
            const int grow = row0 + rr * 8;
            float mx = mrow[rr];
#pragma unroll
            for (int j = 0; j < 16; j++) {
                float s0 = accs[j][rr * 2] * scale;
                float s1 = accs[j][rr * 2 + 1] * scale;
                if (need_mask) {
                    int c0 = kt * FK + j * 8 + tq * 2;
                    if (c0 > grow)     s0 = -1e30f;
                    if (c0 + 1 > grow) s1 = -1e30f;
                }
                accs[j][rr * 2]     = s0;
                accs[j][rr * 2 + 1] = s1;
                mx = fmaxf(mx, fmaxf(s0, s1));
            }
            mx = fmaxf(mx, __shfl_xor_sync(0xFFFFFFFFu, mx, 1));
            mx = fmaxf(mx, __shfl_xor_sync(0xFFFFFFFFu, mx, 2));
            float corr = __expf(mrow[rr] - mx);
            mrow[rr] = mx;
            float ls = 0.f;
#pragma unroll
            for (int j = 0; j < 16; j++) {
                float p0 = __expf(accs[j][rr * 2] - mx);
                float p1 = __expf(accs[j][rr * 2 + 1] - mx);
                accs[j][rr * 2]     = p0;
                accs[j][rr * 2 + 1] = p1;
                ls += p0 + p1;
            }
            ls += __shfl_xor_sync(0xFFFFFFFFu, ls, 1);
            ls += __shfl_xor_sync(0xFFFFFFFFu, ls, 2);
            lrow[rr] = lrow[rr] * corr + ls;
#pragma unroll
            for (int d = 0; d < 16; d++) {
                acc_o[d][rr * 2]     *= corr;
                acc_o[d][rr * 2 + 1] *= corr;
            }
        }

        // ---- P fp16 (C-frag == A-frag identity) ----
        uint32_t p[16][2];
#pragma unroll
        for (int j = 0; j < 16; j++) {
            __half2 h0 = __floats2half2_rn(accs[j][0], accs[j][1]);
            __half2 h1 = __floats2half2_rn(accs[j][2], accs[j][3]);
            p[j][0] = *(uint32_t*)&h0;
            p[j][1] = *(uint32_t*)&h1;
        }

        // ---- O += P @ V ----
#pragma unroll
        for (int kk = 0; kk < 8; kk++) {
            uint32_t a[4] = {p[kk * 2][0], p[kk * 2][1],
                             p[kk * 2 + 1][0], p[kk * 2 + 1][1]};
#pragma unroll
            for (int dn = 0; dn < 8; dn++) {
                uint32_t vb[4];
                int r = kk * 16 + lr;
                LDSM_X4_T(vb, vs + r * 256 + swz(dn * 2 + lq, r) * 16);
                MMA16816(acc_o[dn * 2],     a, vb[0], vb[1]);
                MMA16816(acc_o[dn * 2 + 1], a, vb[2], vb[3]);
            }
        }
        __syncthreads();
    }

    const float il0 = 1.f / lrow[0];
    const float il1 = 1.f / lrow[1];
    __half* Og = Oh + ((size_t)(b * seq + row0) * NH + h) * HD;
#pragma unroll
    for (int dn = 0; dn < 16; dn++) {
        int d = dn * 8 + tq * 2;
        *(__half2*)(Og + d) =
            __floats2half2_rn(acc_o[dn][0] * il0, acc_o[dn][1] * il0);
        *(__half2*)(Og + (size_t)8 * (NH * HD) + d) =
            __floats2half2_rn(acc_o[dn][2] * il1, acc_o[dn][3] * il1);
    }
}

// ---------------- host side ------------------------------------------------
extern "C" void kernel_launch(void* const* d_in, const int* in_sizes, int n_in,
                              void* d_out, int out_size)
{
    const float* x  = (const float*)d_in[0];
    const float* wq = (const float*)d_in[1];
    const float* wk = (const float*)d_in[2];
    const float* wv = (const float*)d_in[3];
    const float* wo = (const float*)d_in[4];
    const float* fc = (const float*)d_in[7];
    const float* fs = (const float*)d_in[8];
    float* out = (float*)d_out;

    __half *xh, *wqkvh, *woh, *attnh, *qh, *kh, *vh;
    cudaGetSymbolAddress((void**)&xh,    g_xh);
    cudaGetSymbolAddress((void**)&wqkvh, g_wqkvh);
    cudaGetSymbolAddress((void**)&woh,   g_woh);
    cudaGetSymbolAddress((void**)&attnh, g_attnh);
    cudaGetSymbolAddress((void**)&qh,    g_qh);
    cudaGetSymbolAddress((void**)&kh,    g_kh);
    cudaGetSymbolAddress((void**)&vh,    g_vh);

    const int M = MTOT;

    convert_all<<<(CQ + 255) / 256, 256>>>(x, wq, wk, wv, wo, xh, wqkvh, woh);

    cudaFuncSetAttribute(gemm_f16_128<0>, cudaFuncAttributeMaxDynamicSharedMemorySize,
                         GEMM_SMEM);
    cudaFuncSetAttribute(gemm_f16_128<1>, cudaFuncAttributeMaxDynamicSharedMemorySize,
                         GEMM_SMEM);

    // fused QKV projection + RoPE + fp16 epilogue
    gemm_f16_128<1><<<dim3(NQKV / GBN, M / GBM), 128, GEMM_SMEM>>>(
        xh, wqkvh, nullptr, qh, kh, vh, fc, fs, M, NQKV, DIMM);

    // fp16 tensor-core flash attention (FK=128)
    cudaFuncSetAttribute(flash_f16, cudaFuncAttributeMaxDynamicSharedMemorySize,
                         FA_SMEM);
    flash_f16<<<dim3(SEQL / FQ, NH, BSZ), 256, FA_SMEM>>>(qh, kh, vh, attnh, SEQL);

    // output projection (fp32 out)
    gemm_f16_128<0><<<dim3(DIMM / GBN, M / GBM), 128, GEMM_SMEM>>>(
        attnh, woh, out, nullptr, nullptr, nullptr, nullptr, nullptr, M, DIMM, DIMM);
}

// round 11
// speedup vs baseline: 1.0496x; 1.0496x over previous
#include <cuda_runtime.h>
#include <cuda_fp16.h>
#include <math.h>
#include <stdint.h>

#define BSZ  2
#define SEQL 2048
#define DIMM 4096
#define NH   32
#define NKV  8
#define HD   128
#define MTOT (BSZ * SEQL)          // 4096
#define NQKV (NH * HD + 2 * NKV * HD)   // 6144

// ---------------- scratch (__device__ globals) ----------------------------
__device__ __half g_xh[MTOT * DIMM];
__device__ __half g_wqkvh[DIMM * NQKV];
__device__ __half g_woh[DIMM * DIMM];
__device__ __half g_attnh[MTOT * NH * HD];
__device__ __half g_qh[MTOT * NH * HD];
__device__ __half g_kh[MTOT * NKV * HD];
__device__ __half g_vh[MTOT * NKV * HD];

// ---------------- PTX helpers ---------------------------------------------
__device__ __forceinline__ uint32_t smem_u32(const void* p) {
    uint32_t a;
    asm("{ .reg .u64 t; cvta.to.shared.u64 t, %1; cvt.u32.u64 %0, t; }"
        : "=r"(a) : "l"(p));
    return a;
}
__device__ __forceinline__ void cp_async16(uint32_t dst, const void* src) {
    asm volatile("cp.async.cg.shared.global [%0], [%1], 16;" :: "r"(dst), "l"(src));
}
#define CP_COMMIT() asm volatile("cp.async.commit_group;" ::: "memory")
#define CP_WAIT(n)  asm volatile("cp.async.wait_group %0;" :: "n"(n) : "memory")

#define LDSM_X4(R, addr) \
    asm volatile("ldmatrix.sync.aligned.m8n8.x4.shared.b16 {%0,%1,%2,%3}, [%4];" \
        : "=r"((R)[0]), "=r"((R)[1]), "=r"((R)[2]), "=r"((R)[3]) : "r"(addr))
#define LDSM_X4_T(R, addr) \
    asm volatile("ldmatrix.sync.aligned.m8n8.x4.trans.shared.b16 {%0,%1,%2,%3}, [%4];" \
        : "=r"((R)[0]), "=r"((R)[1]), "=r"((R)[2]), "=r"((R)[3]) : "r"(addr))

#define MMA16816(D, A, B0, B1) \
    asm volatile("mma.sync.aligned.m16n8k16.row.col.f32.f16.f16.f32 " \
        "{%0,%1,%2,%3}, {%4,%5,%6,%7}, {%8,%9}, {%0,%1,%2,%3};" \
        : "+f"((D)[0]), "+f"((D)[1]), "+f"((D)[2]), "+f"((D)[3]) \
        : "r"((A)[0]), "r"((A)[1]), "r"((A)[2]), "r"((A)[3]), "r"(B0), "r"(B1))

// ---------------- fp16 mma.sync GEMM, 128x128, 3 stages, 2 CTAs/SM --------
// (R9 configuration — 2x4 warp grid, 64x32 warp tiles.)
#define GBM 128
#define GBN 128
#define GBK 64
#define GST 3
#define A_STAGE 16384
#define B_STAGE 16384
#define STAGE_BYTES (A_STAGE + B_STAGE)    // 32768
#define GEMM_SMEM (GST * STAGE_BYTES)      // 98304

template<int MODE>
__global__ __launch_bounds__(256, 2) void gemm_f16_128(
    const __half* __restrict__ A, const __half* __restrict__ B,
    float* __restrict__ C,
    __half* __restrict__ Qd, __half* __restrict__ Kd, __half* __restrict__ Vd,
    const float* __restrict__ cosb, const float* __restrict__ sinb,
    int M, int N, int K)
{
    extern __shared__ char smem[];
    const uint32_t sb = smem_u32(smem);
    const int tid  = threadIdx.x;
    const int lane = tid & 31;
    const int wid  = tid >> 5;
    const int mt   = blockIdx.y * GBM;
    const int nt   = blockIdx.x * GBN;
    const int wm   = (wid >> 2) * 64;
    const int wn   = (wid & 3) * 32;
    const int NK   = K / GBK;

    float acc[4][4][4];
#pragma unroll
    for (int i = 0; i < 4; i++)
#pragma unroll
        for (int j = 0; j < 4; j++)
#pragma unroll
            for (int c = 0; c < 4; c++) acc[i][j][c] = 0.f;

    auto load_stage = [&](int kt, int s) {
        const uint32_t as = sb + s * STAGE_BYTES;
        const uint32_t bs = as + A_STAGE;
        const __half* Ag = A + (size_t)mt * K + kt * GBK;
        const __half* Bg = B + (size_t)(kt * GBK) * N + nt;
#pragma unroll
        for (int i = 0; i < 4; i++) {
            int id = tid + i * 256;
            int r = id >> 3, c = id & 7;
            cp_async16(as + r * 128 + ((c ^ (r & 7)) << 4),
                       Ag + (size_t)r * K + c * 8);
        }
#pragma unroll
        for (int i = 0; i < 4; i++) {
            int id = tid + i * 256;
            int r = id >> 4, c = id & 15;
            uint32_t dst = bs + (c >> 3) * 8192 + r * 128 +
                           (((c & 7) ^ (r & 7)) << 4);
            cp_async16(dst, Bg + (size_t)r * N + c * 8);
        }
        CP_COMMIT();
    };

    load_stage(0, 0);
    load_stage(1, 1);

    const int lr = lane & 15;
    const int lq = lane >> 4;

    int st = 0;
    for (int kt = 0; kt < NK; kt++) {
        CP_WAIT(1);
        __syncthreads();
        if (kt + 2 < NK) {
            int s2 = st + 2; if (s2 >= GST) s2 -= GST;
            load_stage(kt + 2, s2);
        }

        const uint32_t as = sb + st * STAGE_BYTES;
        const uint32_t bs = as + A_STAGE;

#pragma unroll
        for (int ks = 0; ks < 4; ks++) {
            const int kk = ks * 16;
            uint32_t ar[4][4];
#pragma unroll
            for (int mf = 0; mf < 4; mf++) {
                int r = wm + mf * 16 + lr;
                LDSM_X4(ar[mf], as + r * 128 + ((((kk >> 3) + lq) ^ (r & 7)) << 4));
            }
            uint32_t br[2][4];
#pragma unroll
            for (int nf2 = 0; nf2 < 2; nf2++) {
                int n0 = wn + nf2 * 16;
                int r  = kk + lr;
                int cc = ((n0 & 63) >> 3) + lq;
                LDSM_X4_T(br[nf2], bs + ((n0 >= 64) ? 8192 : 0) + r * 128 +
                                   ((cc ^ (r & 7)) << 4));
            }
#pragma unroll
            for (int mf = 0; mf < 4; mf++)
#pragma unroll
                for (int nf = 0; nf < 4; nf++) {
                    uint32_t b0 = br[nf >> 1][(nf & 1) * 2];
                    uint32_t b1 = br[nf >> 1][(nf & 1) * 2 + 1];
                    MMA16816(acc[mf][nf], ar[mf], b0, b1);
                }
        }
        if (++st == GST) st = 0;
    }

    const int g   = lane >> 2;
    const int tq  = lane & 3;

    if (MODE == 0) {
#pragma unroll
        for (int mf = 0; mf < 4; mf++) {
            int row0 = mt + wm + mf * 16 + g;
#pragma unroll
            for (int nf = 0; nf < 4; nf++) {
                int col = nt + wn + nf * 8 + tq * 2;
                *(float2*)(C + (size_t)row0 * N + col) =
                    make_float2(acc[mf][nf][0], acc[mf][nf][1]);
                *(float2*)(C + (size_t)(row0 + 8) * N + col) =
                    make_float2(acc[mf][nf][2], acc[mf][nf][3]);
            }
        }
    } else {
        const int region = (nt >= 5 * 1024) ? 2 : (nt >= 4 * 1024 ? 1 : 0);
        __half* dst = region == 0 ? Qd : (region == 1 ? Kd : Vd);
        const int ld = region == 0 ? NH * HD : NKV * HD;
        const int cb = nt - (region == 0 ? 0 : (region == 1 ? 4096 : 5120));
        const bool dorope = (region < 2);
#pragma unroll
        for (int mf = 0; mf < 4; mf++) {
            int r0 = mt + wm + mf * 16 + g;
            int s0 = r0 & (SEQL - 1);
            int s1 = (r0 + 8) & (SEQL - 1);
#pragma unroll
            for (int nf = 0; nf < 4; nf++) {
                int colg = wn + nf * 8 + tq * 2;
                float a0 = acc[mf][nf][0], a1 = acc[mf][nf][1];
                float a2 = acc[mf][nf][2], a3 = acc[mf][nf][3];
                __half2 h0, h1;
                if (dorope) {
                    int i = ((nt + colg) & 127) >> 1;
                    float c0 = cosb[s0 * 64 + i], n0 = sinb[s0 * 64 + i];
                    float c1 = cosb[s1 * 64 + i], n1 = sinb[s1 * 64 + i];
                    h0 = __floats2half2_rn(a0 * c0 - a1 * n0, a0 * n0 + a1 * c0);
                    h1 = __floats2half2_rn(a2 * c1 - a3 * n1, a2 * n1 + a3 * c1);
                } else {
                    h0 = __floats2half2_rn(a0, a1);
                    h1 = __floats2half2_rn(a2, a3);
                }
                *(__half2*)(dst + (size_t)r0 * ld + cb + colg) = h0;
                *(__half2*)(dst + (size_t)(r0 + 8) * ld + cb + colg) = h1;
            }
        }
    }
}

// ---------------- fused fp32 -> fp16 convert (x, wq|wk|wv only) ------------
#define CNX  (MTOT * DIMM / 8)
#define CNWO (DIMM * DIMM / 8)
#define CNWQ (DIMM * NH * HD / 8)
#define CNWK (DIMM * NKV * HD / 8)
#define CTOT (CNX + CNWQ + 2 * CNWK)     // wo handled inside flash
#define CQ   (CTOT / 4)

__device__ __forceinline__ uint4 cvt8(const float* p) {
    float4 v0 = ((const float4*)p)[0];
    float4 v1 = ((const float4*)p)[1];
    union { uint4 u; __half2 h[4]; } r;
    r.h[0] = __floats2half2_rn(v0.x, v0.y);
    r.h[1] = __floats2half2_rn(v0.z, v0.w);
    r.h[2] = __floats2half2_rn(v1.x, v1.y);
    r.h[3] = __floats2half2_rn(v1.z, v1.w);
    return r.u;
}

__device__ __forceinline__ void do_chunk(
    int i, const float* x, const float* wq, const float* wk,
    const float* wv, __half* xh, __half* wqkvh)
{
    if (i < CNX) {
        ((uint4*)xh)[i] = cvt8(x + (size_t)i * 8);
    } else if (i < CNX + CNWQ) {
        int j = i - CNX;
        int r = j >> 9, c = j & 511;
        *(uint4*)(wqkvh + (size_t)r * NQKV + c * 8) = cvt8(wq + (size_t)j * 8);
    } else if (i < CNX + CNWQ + CNWK) {
        int j = i - CNX - CNWQ;
        int r = j >> 7, c = j & 127;
        *(uint4*)(wqkvh + (size_t)r * NQKV + 4096 + c * 8) = cvt8(wk + (size_t)j * 8);
    } else {
        int j = i - CNX - CNWQ - CNWK;
        int r = j >> 7, c = j & 127;
        *(uint4*)(wqkvh + (size_t)r * NQKV + 5120 + c * 8) = cvt8(wv + (size_t)j * 8);
    }
}

__global__ void convert_all(const float* __restrict__ x,
                            const float* __restrict__ wq,
                            const float* __restrict__ wk,
                            const float* __restrict__ wv,
                            __half* __restrict__ xh,
                            __half* __restrict__ wqkvh)
{
    int i = blockIdx.x * blockDim.x + threadIdx.x;
    if (i >= CQ) return;
    do_chunk(i,          x, wq, wk, wv, xh, wqkvh);
    do_chunk(i + CQ,     x, wq, wk, wv, xh, wqkvh);
    do_chunk(i + 2 * CQ, x, wq, wk, wv, xh, wqkvh);
    do_chunk(i + 3 * CQ, x, wq, wk, wv, xh, wqkvh);
}

// ---------------- fp16 tensor-core flash attention, FK=128 -----------------
// Epilogue additionally converts wo -> fp16 (absorbed by tail imbalance).
#define FQ 128
#define FK 128
#define QBYTES   (FQ * 256)
#define KVSTAGE  (FK * 256 * 2)
#define FA_SMEM  (QBYTES + 2 * KVSTAGE)    // 163840

__device__ __forceinline__ uint32_t swz(uint32_t c, uint32_t r) {
    return ((c ^ (r & 7)) & 7) | (c & 8);
}

__global__ __launch_bounds__(256, 1) void flash_f16(
    const __half* __restrict__ Qh, const __half* __restrict__ Kh,
    const __half* __restrict__ Vh, __half* __restrict__ Oh,
    const float* __restrict__ wo, __half* __restrict__ woh, int seq)
{
    extern __shared__ char smc[];
    const uint32_t sb = smem_u32(smc);
    const uint32_t Qs = sb;

    const int nq = seq / FQ;
    const int qt = nq - 1 - blockIdx.x;       // longest CTAs first
    const int h = blockIdx.y, b = blockIdx.z;
    const int kvh = h >> 2;
    const int tid = threadIdx.x, lane = tid & 31, wid = tid >> 5;
    const int lr = lane & 15, lq = lane >> 4;
    const int g = lane >> 2, tq = lane & 3;
    // scale * log2(e): softmax via exp2
    const float scale2 = 0.08838834764831845f * 1.4426950408889634f;

    const __half* Qg = Qh + ((size_t)(b * seq + qt * FQ) * NH + h) * HD;
    const __half* Kg = Kh + ((size_t)b * seq * NKV + kvh) * HD;
    const __half* Vg = Vh + ((size_t)b * seq * NKV + kvh) * HD;

#pragma unroll
    for (int i = 0; i < 8; i++) {
        int id = tid + i * 256;
        int r = id >> 4, c = id & 15;
        cp_async16(Qs + r * 256 + swz(c, r) * 16, Qg + (size_t)r * (NH * HD) + c * 8);
    }
    CP_COMMIT();

    auto load_kv = [&](int kt, int s) {
        uint32_t ks = sb + QBYTES + s * KVSTAGE;
        uint32_t vs = ks + FK * 256;
        const __half* kg = Kg + (size_t)(kt * FK) * (NKV * HD);
        const __half* vg = Vg + (size_t)(kt * FK) * (NKV * HD);
#pragma unroll
        for (int i = 0; i < 8; i++) {
            int id = tid + i * 256;
            int r = id >> 4, c = id & 15;
            uint32_t off = r * 256 + swz(c, r) * 16;
            cp_async16(ks + off, kg + (size_t)r * (NKV * HD) + c * 8);
            cp_async16(vs + off, vg + (size_t)r * (NKV * HD) + c * 8);
        }
        CP_COMMIT();
    };

    const int ntiles = qt + 1;
    load_kv(0, 0);

    float acc_o[16][4];
#pragma unroll
    for (int d = 0; d < 16; d++)
#pragma unroll
        for (int c = 0; c < 4; c++) acc_o[d][c] = 0.f;
    float mrow[2] = {-1e30f, -1e30f};
    float lrow[2] = {0.f, 0.f};

    const int row0 = qt * FQ + wid * 16 + g;

    for (int kt = 0; kt < ntiles; kt++) {
        if (kt + 1 < ntiles) { load_kv(kt + 1, (kt + 1) & 1); CP_WAIT(1); }
        else                 { CP_WAIT(0); }
        __syncthreads();

        const uint32_t ks = sb + QBYTES + (kt & 1) * KVSTAGE;
        const uint32_t vs = ks + FK * 256;

        float accs[16][4];
#pragma unroll
        for (int j = 0; j < 16; j++)
#pragma unroll
            for (int c = 0; c < 4; c++) accs[j][c] = 0.f;

#pragma unroll
        for (int d = 0; d < 8; d++) {
            uint32_t a[4];
            {
                int r = wid * 16 + lr;
                LDSM_X4(a, Qs + r * 256 + swz(d * 2 + lq, r) * 16);
            }
#pragma unroll
            for (int n = 0; n < 8; n++) {
                uint32_t kb[4];
                int r = n * 16 + lr;
                LDSM_X4(kb, ks + r * 256 + swz(d * 2 + lq, r) * 16);
                MMA16816(accs[n * 2],     a, kb[0], kb[2]);
                MMA16816(accs[n * 2 + 1], a, kb[1], kb[3]);
            }
        }

        const bool need_mask = (kt == qt);
#pragma unroll
        for (int rr = 0; rr < 2; rr++) {
            const int grow = row0 + rr * 8;
            float mx = mrow[rr];
#pragma unroll
            for (int j = 0; j < 16; j++) {
                float s0 = accs[j][rr * 2] * scale2;
                float s1 = accs[j][rr * 2 + 1] * scale2;
                if (need_mask) {
                    int c0 = kt * FK + j * 8 + tq * 2;
                    if (c0 > grow)     s0 = -1e30f;
                    if (c0 + 1 > grow) s1 = -1e30f;
                }
                accs[j][rr * 2]     = s0;
                accs[j][rr * 2 + 1] = s1;
                mx = fmaxf(mx, fmaxf(s0, s1));
            }
            mx = fmaxf(mx, __shfl_xor_sync(0xFFFFFFFFu, mx, 1));
            mx = fmaxf(mx, __shfl_xor_sync(0xFFFFFFFFu, mx, 2));
            float corr = exp2f(mrow[rr] - mx);
            mrow[rr] = mx;
            float ls = 0.f;
#pragma unroll
            for (int j = 0; j < 16; j++) {
                float p0 = exp2f(accs[j][rr * 2] - mx);
                float p1 = exp2f(accs[j][rr * 2 + 1] - mx);
                accs[j][rr * 2]     = p0;
                accs[j][rr * 2 + 1] = p1;
                ls += p0 + p1;
            }
            ls += __shfl_xor_sync(0xFFFFFFFFu, ls, 1);
            ls += __shfl_xor_sync(0xFFFFFFFFu, ls, 2);
            lrow[rr] = lrow[rr] * corr + ls;
#pragma unroll
            for (int d = 0; d < 16; d++) {
                acc_o[d][rr * 2]     *= corr;
                acc_o[d][rr * 2 + 1] *= corr;
            }
        }

        uint32_t p[16][2];
#pragma unroll
        for (int j = 0; j < 16; j++) {
            __half2 h0 = __floats2half2_rn(accs[j][0], accs[j][1]);
            __half2 h1 = __floats2half2_rn(accs[j][2], accs[j][3]);
            p[j][0] = *(uint32_t*)&h0;
            p[j][1] = *(uint32_t*)&h1;
        }

#pragma unroll
        for (int kk = 0; kk < 8; kk++) {
            uint32_t a[4] = {p[kk * 2][0], p[kk * 2][1],
                             p[kk * 2 + 1][0], p[kk * 2 + 1][1]};
#pragma unroll
            for (int dn = 0; dn < 8; dn++) {
                uint32_t vb[4];
                int r = kk * 16 + lr;
                LDSM_X4_T(vb, vs + r * 256 + swz(dn * 2 + lq, r) * 16);
                MMA16816(acc_o[dn * 2],     a, vb[0], vb[1]);
                MMA16816(acc_o[dn * 2 + 1], a, vb[2], vb[3]);
            }
        }
        __syncthreads();
    }

    const float il0 = 1.f / lrow[0];
    const float il1 = 1.f / lrow[1];
    __half* Og = Oh + ((size_t)(b * seq + row0) * NH + h) * HD;
#pragma unroll
    for (int dn = 0; dn < 16; dn++) {
        int d = dn * 8 + tq * 2;
        *(__half2*)(Og + d) =
            __floats2half2_rn(acc_o[dn][0] * il0, acc_o[dn][1] * il0);
        *(__half2*)(Og + (size_t)8 * (NH * HD) + d) =
            __floats2half2_rn(acc_o[dn][2] * il1, acc_o[dn][3] * il1);
    }

    // ---- absorbed work: convert wo -> fp16 (tail-imbalance slack) ----
    {
        const int ncta = gridDim.x * gridDim.y * gridDim.z;   // 1024
        const int cta  = blockIdx.x + gridDim.x * (blockIdx.y + gridDim.y * blockIdx.z);
        const int nthr = ncta * 256;
        for (int i = cta * 256 + tid; i < CNWO; i += nthr)
            ((uint4*)woh)[i] = cvt8(wo + (size_t)i * 8);
    }
}

// ---------------- host side ------------------------------------------------
extern "C" void kernel_launch(void* const* d_in, const int* in_sizes, int n_in,
                              void* d_out, int out_size)
{
    const float* x  = (const float*)d_in[0];
    const float* wq = (const float*)d_in[1];
    const float* wk = (const float*)d_in[2];
    const float* wv = (const float*)d_in[3];
    const float* wo = (const float*)d_in[4];
    const float* fc = (const float*)d_in[7];
    const float* fs = (const float*)d_in[8];
    float* out = (float*)d_out;

    __half *xh, *wqkvh, *woh, *attnh, *qh, *kh, *vh;
    cudaGetSymbolAddress((void**)&xh,    g_xh);
    cudaGetSymbolAddress((void**)&wqkvh, g_wqkvh);
    cudaGetSymbolAddress((void**)&woh,   g_woh);
    cudaGetSymbolAddress((void**)&attnh, g_attnh);
    cudaGetSymbolAddress((void**)&qh,    g_qh);
    cudaGetSymbolAddress((void**)&kh,    g_kh);
    cudaGetSymbolAddress((void**)&vh,    g_vh);

    const int M = MTOT;

    // convert x + wq|wk|wv (wo converted inside flash)
    convert_all<<<(CQ + 255) / 256, 256>>>(x, wq, wk, wv, xh, wqkvh);

    cudaFuncSetAttribute(gemm_f16_128<0>, cudaFuncAttributeMaxDynamicSharedMemorySize,
                         GEMM_SMEM);
    cudaFuncSetAttribute(gemm_f16_128<1>, cudaFuncAttributeMaxDynamicSharedMemorySize,
                         GEMM_SMEM);

    // fused QKV projection + RoPE + fp16 epilogue
    gemm_f16_128<1><<<dim3(NQKV / GBN, M / GBM), 256, GEMM_SMEM>>>(
        xh, wqkvh, nullptr, qh, kh, vh, fc, fs, M, NQKV, DIMM);

    // fp16 tensor-core flash attention (FK=128) + wo convert epilogue
    cudaFuncSetAttribute(flash_f16, cudaFuncAttributeMaxDynamicSharedMemorySize,
                         FA_SMEM);
    flash_f16<<<dim3(SEQL / FQ, NH, BSZ), 256, FA_SMEM>>>(
        qh, kh, vh, attnh, wo, woh, SEQL);

    // output projection (fp32 out)
    gemm_f16_128<0><<<dim3(DIMM / GBN, M / GBM), 256, GEMM_SMEM>>>(
        attnh, woh, out, nullptr, nullptr, nullptr, nullptr, nullptr, M, DIMM, DIMM);
}

// round 12
// speedup vs baseline: 1.0712x; 1.0206x over previous
#include <cuda_runtime.h>
#include <cuda_fp16.h>
#include <math.h>
#include <stdint.h>

#define BSZ  2
#define SEQL 2048
#define DIMM 4096
#define NH   32
#define NKV  8
#define HD   128
#define MTOT (BSZ * SEQL)          // 4096
#define NQKV (NH * HD + 2 * NKV * HD)   // 6144

// ---------------- scratch (__device__ globals) ----------------------------
__device__ __half g_xh[MTOT * DIMM];
__device__ __half g_wqkvh[DIMM * NQKV];
__device__ __half g_woh[DIMM * DIMM];
__device__ __half g_attnh[MTOT * NH * HD];
__device__ __half g_qh[MTOT * NH * HD];
__device__ __half g_kh[MTOT * NKV * HD];
__device__ __half g_vh[MTOT * NKV * HD];

// ---------------- PTX helpers ---------------------------------------------
__device__ __forceinline__ uint32_t smem_u32(const void* p) {
    uint32_t a;
    asm("{ .reg .u64 t; cvta.to.shared.u64 t, %1; cvt.u32.u64 %0, t; }"
        : "=r"(a) : "l"(p));
    return a;
}
__device__ __forceinline__ void cp_async16(uint32_t dst, const void* src) {
    asm volatile("cp.async.cg.shared.global [%0], [%1], 16;" :: "r"(dst), "l"(src));
}
#define CP_COMMIT() asm volatile("cp.async.commit_group;" ::: "memory")
#define CP_WAIT(n)  asm volatile("cp.async.wait_group %0;" :: "n"(n) : "memory")

#define LDSM_X4(R, addr) \
    asm volatile("ldmatrix.sync.aligned.m8n8.x4.shared.b16 {%0,%1,%2,%3}, [%4];" \
        : "=r"((R)[0]), "=r"((R)[1]), "=r"((R)[2]), "=r"((R)[3]) : "r"(addr))
#define LDSM_X4_T(R, addr) \
    asm volatile("ldmatrix.sync.aligned.m8n8.x4.trans.shared.b16 {%0,%1,%2,%3}, [%4];" \
        : "=r"((R)[0]), "=r"((R)[1]), "=r"((R)[2]), "=r"((R)[3]) : "r"(addr))

#define MMA16816(D, A, B0, B1) \
    asm volatile("mma.sync.aligned.m16n8k16.row.col.f32.f16.f16.f32 " \
        "{%0,%1,%2,%3}, {%4,%5,%6,%7}, {%8,%9}, {%0,%1,%2,%3};" \
        : "+f"((D)[0]), "+f"((D)[1]), "+f"((D)[2]), "+f"((D)[3]) \
        : "r"((A)[0]), "r"((A)[1]), "r"((A)[2]), "r"((A)[3]), "r"(B0), "r"(B1))

// ---------------- fp16 mma.sync GEMM, 128x128, 3 stages, 2 CTAs/SM --------
// (R9 configuration — 2x4 warp grid, 64x32 warp tiles.)
#define GBM 128
#define GBN 128
#define GBK 64
#define GST 3
#define A_STAGE 16384
#define B_STAGE 16384
#define STAGE_BYTES (A_STAGE + B_STAGE)    // 32768
#define GEMM_SMEM (GST * STAGE_BYTES)      // 98304

template<int MODE>
__global__ __launch_bounds__(256, 2) void gemm_f16_128(
    const __half* __restrict__ A, const __half* __restrict__ B,
    float* __restrict__ C,
    __half* __restrict__ Qd, __half* __restrict__ Kd, __half* __restrict__ Vd,
    const float* __restrict__ cosb, const float* __restrict__ sinb,
    int M, int N, int K)
{
    extern __shared__ char smem[];
    const uint32_t sb = smem_u32(smem);
    const int tid  = threadIdx.x;
    const int lane = tid & 31;
    const int wid  = tid >> 5;
    const int mt   = blockIdx.y * GBM;
    const int nt   = blockIdx.x * GBN;
    const int wm   = (wid >> 2) * 64;
    const int wn   = (wid & 3) * 32;
    const int NK   = K / GBK;

    float acc[4][4][4];
#pragma unroll
    for (int i = 0; i < 4; i++)
#pragma unroll
        for (int j = 0; j < 4; j++)
#pragma unroll
            for (int c = 0; c < 4; c++) acc[i][j][c] = 0.f;

    auto load_stage = [&](int kt, int s) {
        const uint32_t as = sb + s * STAGE_BYTES;
        const uint32_t bs = as + A_STAGE;
        const __half* Ag = A + (size_t)mt * K + kt * GBK;
        const __half* Bg = B + (size_t)(kt * GBK) * N + nt;
#pragma unroll
        for (int i = 0; i < 4; i++) {
            int id = tid + i * 256;
            int r = id >> 3, c = id & 7;
            cp_async16(as + r * 128 + ((c ^ (r & 7)) << 4),
                       Ag + (size_t)r * K + c * 8);
        }
#pragma unroll
        for (int i = 0; i < 4; i++) {
            int id = tid + i * 256;
            int r = id >> 4, c = id & 15;
            uint32_t dst = bs + (c >> 3) * 8192 + r * 128 +
                           (((c & 7) ^ (r & 7)) << 4);
            cp_async16(dst, Bg + (size_t)r * N + c * 8);
        }
        CP_COMMIT();
    };

    load_stage(0, 0);
    load_stage(1, 1);

    const int lr = lane & 15;
    const int lq = lane >> 4;

    int st = 0;
    for (int kt = 0; kt < NK; kt++) {
        CP_WAIT(1);
        __syncthreads();
        if (kt + 2 < NK) {
            int s2 = st + 2; if (s2 >= GST) s2 -= GST;
            load_stage(kt + 2, s2);
        }

        const uint32_t as = sb + st * STAGE_BYTES;
        const uint32_t bs = as + A_STAGE;

#pragma unroll
        for (int ks = 0; ks < 4; ks++) {
            const int kk = ks * 16;
            uint32_t ar[4][4];
#pragma unroll
            for (int mf = 0; mf < 4; mf++) {
                int r = wm + mf * 16 + lr;
                LDSM_X4(ar[mf], as + r * 128 + ((((kk >> 3) + lq) ^ (r & 7)) << 4));
            }
            uint32_t br[2][4];
#pragma unroll
            for (int nf2 = 0; nf2 < 2; nf2++) {
                int n0 = wn + nf2 * 16;
                int r  = kk + lr;
                int cc = ((n0 & 63) >> 3) + lq;
                LDSM_X4_T(br[nf2], bs + ((n0 >= 64) ? 8192 : 0) + r * 128 +
                                   ((cc ^ (r & 7)) << 4));
            }
#pragma unroll
            for (int mf = 0; mf < 4; mf++)
#pragma unroll
                for (int nf = 0; nf < 4; nf++) {
                    uint32_t b0 = br[nf >> 1][(nf & 1) * 2];
                    uint32_t b1 = br[nf >> 1][(nf & 1) * 2 + 1];
                    MMA16816(acc[mf][nf], ar[mf], b0, b1);
                }
        }
        if (++st == GST) st = 0;
    }

    const int g   = lane >> 2;
    const int tq  = lane & 3;

    if (MODE == 0) {
#pragma unroll
        for (int mf = 0; mf < 4; mf++) {
            int row0 = mt + wm + mf * 16 + g;
#pragma unroll
            for (int nf = 0; nf < 4; nf++) {
                int col = nt + wn + nf * 8 + tq * 2;
                *(float2*)(C + (size_t)row0 * N + col) =
                    make_float2(acc[mf][nf][0], acc[mf][nf][1]);
                *(float2*)(C + (size_t)(row0 + 8) * N + col) =
                    make_float2(acc[mf][nf][2], acc[mf][nf][3]);
            }
        }
    } else {
        const int region = (nt >= 5 * 1024) ? 2 : (nt >= 4 * 1024 ? 1 : 0);
        __half* dst = region == 0 ? Qd : (region == 1 ? Kd : Vd);
        const int ld = region == 0 ? NH * HD : NKV * HD;
        const int cb = nt - (region == 0 ? 0 : (region == 1 ? 4096 : 5120));
        const bool dorope = (region < 2);
#pragma unroll
        for (int mf = 0; mf < 4; mf++) {
            int r0 = mt + wm + mf * 16 + g;
            int s0 = r0 & (SEQL - 1);
            int s1 = (r0 + 8) & (SEQL - 1);
#pragma unroll
            for (int nf = 0; nf < 4; nf++) {
                int colg = wn + nf * 8 + tq * 2;
                float a0 = acc[mf][nf][0], a1 = acc[mf][nf][1];
                float a2 = acc[mf][nf][2], a3 = acc[mf][nf][3];
                __half2 h0, h1;
                if (dorope) {
                    int i = ((nt + colg) & 127) >> 1;
                    float c0 = cosb[s0 * 64 + i], n0 = sinb[s0 * 64 + i];
                    float c1 = cosb[s1 * 64 + i], n1 = sinb[s1 * 64 + i];
                    h0 = __floats2half2_rn(a0 * c0 - a1 * n0, a0 * n0 + a1 * c0);
                    h1 = __floats2half2_rn(a2 * c1 - a3 * n1, a2 * n1 + a3 * c1);
                } else {
                    h0 = __floats2half2_rn(a0, a1);
                    h1 = __floats2half2_rn(a2, a3);
                }
                *(__half2*)(dst + (size_t)r0 * ld + cb + colg) = h0;
                *(__half2*)(dst + (size_t)(r0 + 8) * ld + cb + colg) = h1;
            }
        }
    }
}

// ---------------- fused fp32 -> fp16 convert (x, wq|wk|wv only) ------------
#define CNX  (MTOT * DIMM / 8)
#define CNWO (DIMM * DIMM / 8)
#define CNWQ (DIMM * NH * HD / 8)
#define CNWK (DIMM * NKV * HD / 8)
#define CTOT (CNX + CNWQ + 2 * CNWK)     // wo handled inside flash
#define CQ   (CTOT / 4)

__device__ __forceinline__ uint4 cvt8(const float* p) {
    float4 v0 = ((const float4*)p)[0];
    float4 v1 = ((const float4*)p)[1];
    union { uint4 u; __half2 h[4]; } r;
    r.h[0] = __floats2half2_rn(v0.x, v0.y);
    r.h[1] = __floats2half2_rn(v0.z, v0.w);
    r.h[2] = __floats2half2_rn(v1.x, v1.y);
    r.h[3] = __floats2half2_rn(v1.z, v1.w);
    return r.u;
}

__device__ __forceinline__ void do_chunk(
    int i, const float* x, const float* wq, const float* wk,
    const float* wv, __half* xh, __half* wqkvh)
{
    if (i < CNX) {
        ((uint4*)xh)[i] = cvt8(x + (size_t)i * 8);
    } else if (i < CNX + CNWQ) {
        int j = i - CNX;
        int r = j >> 9, c = j & 511;
        *(uint4*)(wqkvh + (size_t)r * NQKV + c * 8) = cvt8(wq + (size_t)j * 8);
    } else if (i < CNX + CNWQ + CNWK) {
        int j = i - CNX - CNWQ;
        int r = j >> 7, c = j & 127;
        *(uint4*)(wqkvh + (size_t)r * NQKV + 4096 + c * 8) = cvt8(wk + (size_t)j * 8);
    } else {
        int j = i - CNX - CNWQ - CNWK;
        int r = j >> 7, c = j & 127;
        *(uint4*)(wqkvh + (size_t)r * NQKV + 5120 + c * 8) = cvt8(wv + (size_t)j * 8);
    }
}

__global__ void convert_all(const float* __restrict__ x,
                            const float* __restrict__ wq,
                            const float* __restrict__ wk,
                            const float* __restrict__ wv,
                            __half* __restrict__ xh,
                            __half* __restrict__ wqkvh)
{
    int i = blockIdx.x * blockDim.x + threadIdx.x;
    if (i >= CQ) return;
    do_chunk(i,          x, wq, wk, wv, xh, wqkvh);
    do_chunk(i + CQ,     x, wq, wk, wv, xh, wqkvh);
    do_chunk(i + 2 * CQ, x, wq, wk, wv, xh, wqkvh);
    do_chunk(i + 3 * CQ, x, wq, wk, wv, xh, wqkvh);
}

// ------- fp16 flash attention: FQ=64, FK=64, 128 thr, 2 CTAs/SM -----------
// Softmax of one CTA overlaps tensor work of the co-resident CTA.
// Epilogue also converts wo -> fp16 (grid-stride).
#define FQ 64
#define FK 64
#define QBYTES   (FQ * 256)                // 16384
#define KVSTAGE  (FK * 256 * 2)            // 32768 (K 16KB + V 16KB)
#define FA_SMEM  (QBYTES + 2 * KVSTAGE)    // 81920

__device__ __forceinline__ uint32_t swz(uint32_t c, uint32_t r) {
    return ((c ^ (r & 7)) & 7) | (c & 8);
}

__global__ __launch_bounds__(128, 2) void flash_f16(
    const __half* __restrict__ Qh, const __half* __restrict__ Kh,
    const __half* __restrict__ Vh, __half* __restrict__ Oh,
    const float* __restrict__ wo, __half* __restrict__ woh, int seq)
{
    extern __shared__ char smc[];
    const uint32_t sb = smem_u32(smc);
    const uint32_t Qs = sb;

    const int nq = seq / FQ;
    const int qt = nq - 1 - blockIdx.x;       // longest CTAs first
    const int h = blockIdx.y, b = blockIdx.z;
    const int kvh = h >> 2;
    const int tid = threadIdx.x, lane = tid & 31, wid = tid >> 5; // wid 0..3
    const int lr = lane & 15, lq = lane >> 4;
    const int g = lane >> 2, tq = lane & 3;
    const float scale2 = 0.08838834764831845f * 1.4426950408889634f;

    const __half* Qg = Qh + ((size_t)(b * seq + qt * FQ) * NH + h) * HD;
    const __half* Kg = Kh + ((size_t)b * seq * NKV + kvh) * HD;
    const __half* Vg = Vh + ((size_t)b * seq * NKV + kvh) * HD;

    // Q tile: 64 rows x 256 B = 1024 chunks over 128 threads
#pragma unroll
    for (int i = 0; i < 8; i++) {
        int id = tid + i * 128;
        int r = id >> 4, c = id & 15;
        cp_async16(Qs + r * 256 + swz(c, r) * 16, Qg + (size_t)r * (NH * HD) + c * 8);
    }
    CP_COMMIT();

    auto load_kv = [&](int kt, int s) {
        uint32_t ks = sb + QBYTES + s * KVSTAGE;
        uint32_t vs = ks + FK * 256;
        const __half* kg = Kg + (size_t)(kt * FK) * (NKV * HD);
        const __half* vg = Vg + (size_t)(kt * FK) * (NKV * HD);
#pragma unroll
        for (int i = 0; i < 8; i++) {
            int id = tid + i * 128;
            int r = id >> 4, c = id & 15;
            uint32_t off = r * 256 + swz(c, r) * 16;
            cp_async16(ks + off, kg + (size_t)r * (NKV * HD) + c * 8);
            cp_async16(vs + off, vg + (size_t)r * (NKV * HD) + c * 8);
        }
        CP_COMMIT();
    };

    const int ntiles = qt + 1;
    load_kv(0, 0);

    // Wait for Q + kv0, hoist Q fragments into registers (reused all tiles)
    CP_WAIT(0);
    __syncthreads();
    uint32_t qf[8][4];
#pragma unroll
    for (int d = 0; d < 8; d++) {
        int r = wid * 16 + lr;
        LDSM_X4(qf[d], Qs + r * 256 + swz(d * 2 + lq, r) * 16);
    }

    float acc_o[16][4];
#pragma unroll
    for (int d = 0; d < 16; d++)
#pragma unroll
        for (int c = 0; c < 4; c++) acc_o[d][c] = 0.f;
    float mrow[2] = {-1e30f, -1e30f};
    float lrow[2] = {0.f, 0.f};

    const int row0 = qt * FQ + wid * 16 + g;

    for (int kt = 0; kt < ntiles; kt++) {
        if (kt + 1 < ntiles) { load_kv(kt + 1, (kt + 1) & 1); CP_WAIT(1); }
        else                 { CP_WAIT(0); }
        __syncthreads();

        const uint32_t ks = sb + QBYTES + (kt & 1) * KVSTAGE;
        const uint32_t vs = ks + FK * 256;

        // ---- S = Q @ K^T  (warp tile 16 x 64) ----
        float accs[8][4];
#pragma unroll
        for (int j = 0; j < 8; j++)
#pragma unroll
            for (int c = 0; c < 4; c++) accs[j][c] = 0.f;

#pragma unroll
        for (int d = 0; d < 8; d++) {
#pragma unroll
            for (int n = 0; n < 4; n++) {
                uint32_t kb[4];
                int r = n * 16 + lr;
                LDSM_X4(kb, ks + r * 256 + swz(d * 2 + lq, r) * 16);
                MMA16816(accs[n * 2],     qf[d], kb[0], kb[2]);
                MMA16816(accs[n * 2 + 1], qf[d], kb[1], kb[3]);
            }
        }

        // ---- online softmax (exp2) ----
        const bool need_mask = (kt == qt);
#pragma unroll
        for (int rr = 0; rr < 2; rr++) {
            const int grow = row0 + rr * 8;
            float mx = mrow[rr];
#pragma unroll
            for (int j = 0; j < 8; j++) {
                float s0 = accs[j][rr * 2] * scale2;
                float s1 = accs[j][rr * 2 + 1] * scale2;
                if (need_mask) {
                    int c0 = kt * FK + j * 8 + tq * 2;
                    if (c0 > grow)     s0 = -1e30f;
                    if (c0 + 1 > grow) s1 = -1e30f;
                }
                accs[j][rr * 2]     = s0;
                accs[j][rr * 2 + 1] = s1;
                mx = fmaxf(mx, fmaxf(s0, s1));
            }
            mx = fmaxf(mx, __shfl_xor_sync(0xFFFFFFFFu, mx, 1));
            mx = fmaxf(mx, __shfl_xor_sync(0xFFFFFFFFu, mx, 2));
            float corr = exp2f(mrow[rr] - mx);
            mrow[rr] = mx;
            float ls = 0.f;
#pragma unroll
            for (int j = 0; j < 8; j++) {
                float p0 = exp2f(accs[j][rr * 2] - mx);
                float p1 = exp2f(accs[j][rr * 2 + 1] - mx);
                accs[j][rr * 2]     = p0;
                accs[j][rr * 2 + 1] = p1;
                ls += p0 + p1;
            }
            ls += __shfl_xor_sync(0xFFFFFFFFu, ls, 1);
            ls += __shfl_xor_sync(0xFFFFFFFFu, ls, 2);
            lrow[rr] = lrow[rr] * corr + ls;
#pragma unroll
            for (int d = 0; d < 16; d++) {
                acc_o[d][rr * 2]     *= corr;
                acc_o[d][rr * 2 + 1] *= corr;
            }
        }

        // ---- P fp16 (C-frag == A-frag identity) ----
        uint32_t p[8][2];
#pragma unroll
        for (int j = 0; j < 8; j++) {
            __half2 h0 = __floats2half2_rn(accs[j][0], accs[j][1]);
            __half2 h1 = __floats2half2_rn(accs[j][2], accs[j][3]);
            p[j][0] = *(uint32_t*)&h0;
            p[j][1] = *(uint32_t*)&h1;
        }

        // ---- O += P @ V ----
#pragma unroll
        for (int kk = 0; kk < 4; kk++) {
            uint32_t a[4] = {p[kk * 2][0], p[kk * 2][1],
                             p[kk * 2 + 1][0], p[kk * 2 + 1][1]};
#pragma unroll
            for (int dn = 0; dn < 8; dn++) {
                uint32_t vb[4];
                int r = kk * 16 + lr;
                LDSM_X4_T(vb, vs + r * 256 + swz(dn * 2 + lq, r) * 16);
                MMA16816(acc_o[dn * 2],     a, vb[0], vb[1]);
                MMA16816(acc_o[dn * 2 + 1], a, vb[2], vb[3]);
            }
        }
        __syncthreads();
    }

    const float il0 = 1.f / lrow[0];
    const float il1 = 1.f / lrow[1];
    __half* Og = Oh + ((size_t)(b * seq + row0) * NH + h) * HD;
#pragma unroll
    for (int dn = 0; dn < 16; dn++) {
        int d = dn * 8 + tq * 2;
        *(__half2*)(Og + d) =
            __floats2half2_rn(acc_o[dn][0] * il0, acc_o[dn][1] * il0);
        *(__half2*)(Og + (size_t)8 * (NH * HD) + d) =
            __floats2half2_rn(acc_o[dn][2] * il1, acc_o[dn][3] * il1);
    }

    // ---- absorbed work: convert wo -> fp16 (tail-imbalance slack) ----
    {
        const int ncta = gridDim.x * gridDim.y * gridDim.z;   // 2048
        const int cta  = blockIdx.x + gridDim.x * (blockIdx.y + gridDim.y * blockIdx.z);
        const int nthr = ncta * 128;
        for (int i = cta * 128 + tid; i < CNWO; i += nthr)
            ((uint4*)woh)[i] = cvt8(wo + (size_t)i * 8);
    }
}

// ---------------- host side ------------------------------------------------
extern "C" void kernel_launch(void* const* d_in, const int* in_sizes, int n_in,
                              void* d_out, int out_size)
{
    const float* x  = (const float*)d_in[0];
    const float* wq = (const float*)d_in[1];
    const float* wk = (const float*)d_in[2];
    const float* wv = (const float*)d_in[3];
    const float* wo = (const float*)d_in[4];
    const float* fc = (const float*)d_in[7];
    const float* fs = (const float*)d_in[8];
    float* out = (float*)d_out;

    __half *xh, *wqkvh, *woh, *attnh, *qh, *kh, *vh;
    cudaGetSymbolAddress((void**)&xh,    g_xh);
    cudaGetSymbolAddress((void**)&wqkvh, g_wqkvh);
    cudaGetSymbolAddress((void**)&woh,   g_woh);
    cudaGetSymbolAddress((void**)&attnh, g_attnh);
    cudaGetSymbolAddress((void**)&qh,    g_qh);
    cudaGetSymbolAddress((void**)&kh,    g_kh);
    cudaGetSymbolAddress((void**)&vh,    g_vh);

    const int M = MTOT;

    // convert x + wq|wk|wv (wo converted inside flash)
    convert_all<<<(CQ + 255) / 256, 256>>>(x, wq, wk, wv, xh, wqkvh);

    cudaFuncSetAttribute(gemm_f16_128<0>, cudaFuncAttributeMaxDynamicSharedMemorySize,
                         GEMM_SMEM);
    cudaFuncSetAttribute(gemm_f16_128<1>, cudaFuncAttributeMaxDynamicSharedMemorySize,
                         GEMM_SMEM);

    // fused QKV projection + RoPE + fp16 epilogue
    gemm_f16_128<1><<<dim3(NQKV / GBN, M / GBM), 256, GEMM_SMEM>>>(
        xh, wqkvh, nullptr, qh, kh, vh, fc, fs, M, NQKV, DIMM);

    // fp16 flash attention (FQ=64, 2 CTAs/SM) + wo convert epilogue
    cudaFuncSetAttribute(flash_f16, cudaFuncAttributeMaxDynamicSharedMemorySize,
                         FA_SMEM);
    flash_f16<<<dim3(SEQL / FQ, NH, BSZ), 128, FA_SMEM>>>(
        qh, kh, vh, attnh, wo, woh, SEQL);

    // output projection (fp32 out)
    gemm_f16_128<0><<<dim3(DIMM / GBN, M / GBM), 256, GEMM_SMEM>>>(
        attnh, woh, out, nullptr, nullptr, nullptr, nullptr, nullptr, M, DIMM, DIMM);
}